// round 15
// baseline (speedup 1.0000x reference)
#include <cuda_runtime.h>
#include <cuda_fp16.h>

#define NN 50000
#define NE 500000
#define D 128
#define TDIM 32
#define EDIM 160
#define TE 32         // edges per block (edge kernel)
#define SAH 168       // attr tile smem stride (halves)
#define SEH 68        // e-result smem stride (half2)
#define SXH 136       // x tile smem stride (halves)

// ---- scratch (no cudaMalloc allowed) ----
__device__ __half2 g_qh[NN * 64];
__device__ __half2 g_kh[NN * 64];
__device__ __half2 g_vh[NN * 64];
__device__ float   g_agg[NN * D];
__device__ float   g_sum[NN * 2];
__device__ __half2 g_we_h2[80 * D];          // pre-swizzled fp16 We (k-pairs)
__device__ __half2 g_w_h2[4 * 64 * D];       // pre-swizzled fp16 Wq|Wk|Wv|Wskip
__device__ int     g_idx64;

// ---- helpers ----
__device__ __forceinline__ void red_v4(float* p, float a, float b, float c, float d) {
    asm volatile("red.global.add.v4.f32 [%0], {%1,%2,%3,%4};"
                 :: "l"(p), "f"(a), "f"(b), "f"(c), "f"(d) : "memory");
}
__device__ __forceinline__ void red_1(float* p, float a) {
    asm volatile("red.global.add.f32 [%0], %1;" :: "l"(p), "f"(a) : "memory");
}
__device__ __forceinline__ void mma_f16(float* c, const unsigned* a,
                                        unsigned b0, unsigned b1) {
    asm volatile(
        "mma.sync.aligned.m16n8k16.row.col.f32.f16.f16.f32 "
        "{%0,%1,%2,%3}, {%4,%5,%6,%7}, {%8,%9}, {%0,%1,%2,%3};"
        : "+f"(c[0]), "+f"(c[1]), "+f"(c[2]), "+f"(c[3])
        : "r"(a[0]), "r"(a[1]), "r"(a[2]), "r"(a[3]), "r"(b0), "r"(b1));
}

// ---- prep: detect idx width + pre-swizzle weights + zero agg/sum (one launch) ----
__global__ void prep_kernel(const long long* __restrict__ ei,
                            const float* __restrict__ We,
                            const float* __restrict__ Wq,
                            const float* __restrict__ Wk,
                            const float* __restrict__ Wv,
                            const float* __restrict__ Ws) {
    const int i = blockIdx.x * blockDim.x + threadIdx.x;
    const int stride = gridDim.x * blockDim.x;
    if (i == 0) {
        bool ok = true;
        #pragma unroll
        for (int j = 0; j < 16; j++) {
            long long v = ei[j];
            if (v < 0 || v >= NN) ok = false;
        }
        g_idx64 = ok ? 1 : 0;
    }
    if (i < 80 * D) {                     // We: 80 k-pairs x 128 cols
        const int p = i >> 7, c = i & 127;
        const int s = (c >> 6) * 64 + (c & 7) * 8 + ((c >> 3) & 7);
        g_we_h2[p * D + s] = __floats2half2_rn(__ldg(We + (2 * p) * D + c),
                                               __ldg(We + (2 * p + 1) * D + c));
    }
    if (i < 4 * 64 * D) {                 // Wq|Wk|Wv|Ws: 64 k-pairs each
        const int mat = i >> 13, rem = i & 8191;
        const int p = rem >> 7, c = rem & 127;
        const int s = (c >> 6) * 64 + (c & 7) * 8 + ((c >> 3) & 7);
        const float* W = (mat == 0) ? Wq : (mat == 1) ? Wk : (mat == 2) ? Wv : Ws;
        g_w_h2[mat * 64 * D + p * D + s] =
            __floats2half2_rn(__ldg(W + (2 * p) * D + c), __ldg(W + (2 * p + 1) * D + c));
    }
    const float4 z = make_float4(0, 0, 0, 0);
    for (int j = i; j < NN * 32; j += stride) ((float4*)g_agg)[j] = z;
    for (int j = i; j < NN / 2;  j += stride) ((float4*)g_sum)[j] = z;
}

// ---- proj (fp16 mma): q,k,v,skip = x @ W + b. grid = (nodeTiles, 4 mats) ----
__global__ __launch_bounds__(256, 2) void proj_kernel(
    const float* __restrict__ x,
    const float* __restrict__ bq, const float* __restrict__ bk,
    const float* __restrict__ bv, const float* __restrict__ bs,
    float* __restrict__ out)
{
    extern __shared__ __half sX[];   // [128][SXH] fp16 x tile (34.8KB)
    const int tid = threadIdx.x;
    const int n0  = blockIdx.x * 128;
    const int mat = blockIdx.y;

    for (int i = tid; i < 128 * 32; i += 256) {
        const int n = i >> 5, q = i & 31;
        float4 m = make_float4(0, 0, 0, 0);
        if (n0 + n < NN) m = __ldg((const float4*)(x + (size_t)(n0 + n) * D) + q);
        __half2* p = (__half2*)(sX + n * SXH + 4 * q);
        p[0] = __floats2half2_rn(m.x, m.y);
        p[1] = __floats2half2_rn(m.z, m.w);
    }
    __syncthreads();

    const int wid = tid >> 5, lane = tid & 31;
    const int g = lane >> 2, tg = lane & 3;
    const int wm = wid & 3, wn = wid >> 2;

    float acc[2][8][4];
    #pragma unroll
    for (int mi = 0; mi < 2; mi++)
        #pragma unroll
        for (int ni = 0; ni < 8; ni++)
            #pragma unroll
            for (int r = 0; r < 4; r++) acc[mi][ni][r] = 0.f;

    const __half*  Abase = sX + (wm * 32 + g) * SXH + 2 * tg;
    const __half2* Bb    = g_w_h2 + mat * 64 * D + wn * 64 + g * 8;

    #pragma unroll
    for (int ks = 0; ks < 8; ks++) {             // 8 k16-steps, K=128
        const int k0 = ks * 16;
        unsigned a[2][4];
        #pragma unroll
        for (int mi = 0; mi < 2; mi++) {
            const __half* ap = Abase + mi * 16 * SXH + k0;
            a[mi][0] = *(const unsigned*)(ap);
            a[mi][1] = *(const unsigned*)(ap + 8 * SXH);
            a[mi][2] = *(const unsigned*)(ap + 8);
            a[mi][3] = *(const unsigned*)(ap + 8 * SXH + 8);
        }
        const uint4* bp0 = (const uint4*)(Bb + (size_t)(ks * 8 + tg) * D);
        const uint4* bp1 = (const uint4*)(Bb + (size_t)(ks * 8 + tg + 4) * D);
        const uint4 u0 = __ldg(bp0), u1 = __ldg(bp0 + 1);
        const uint4 v0 = __ldg(bp1), v1 = __ldg(bp1 + 1);
        const unsigned b0[8] = {u0.x, u0.y, u0.z, u0.w, u1.x, u1.y, u1.z, u1.w};
        const unsigned b1[8] = {v0.x, v0.y, v0.z, v0.w, v1.x, v1.y, v1.z, v1.w};
        #pragma unroll
        for (int ni = 0; ni < 8; ni++) {
            mma_f16(acc[0][ni], a[0], b0[ni], b1[ni]);
            mma_f16(acc[1][ni], a[1], b0[ni], b1[ni]);
        }
    }

    const float* bias = (mat == 0) ? bq : (mat == 1) ? bk : (mat == 2) ? bv : bs;

    #pragma unroll
    for (int mi = 0; mi < 2; mi++) {
        const int r0 = n0 + wm * 32 + mi * 16 + g;
        #pragma unroll
        for (int ni = 0; ni < 8; ni++) {
            const int c = wn * 64 + ni * 8 + 2 * tg;
            const float2 bb = __ldg((const float2*)(bias + c));
            if (mat == 3) {
                if (r0 < NN)
                    *(float2*)(out + (size_t)r0 * D + c) =
                        make_float2(acc[mi][ni][0] + bb.x, acc[mi][ni][1] + bb.y);
                if (r0 + 8 < NN)
                    *(float2*)(out + (size_t)(r0 + 8) * D + c) =
                        make_float2(acc[mi][ni][2] + bb.x, acc[mi][ni][3] + bb.y);
            } else {
                __half2* dst = (mat == 0) ? g_qh : (mat == 1) ? g_kh : g_vh;
                const int hc = c >> 1;
                if (r0 < NN)
                    dst[(size_t)r0 * 64 + hc] =
                        __floats2half2_rn(acc[mi][ni][0] + bb.x, acc[mi][ni][1] + bb.y);
                if (r0 + 8 < NN)
                    dst[(size_t)(r0 + 8) * 64 + hc] =
                        __floats2half2_rn(acc[mi][ni][2] + bb.x, acc[mi][ni][3] + bb.y);
            }
        }
    }
}

// ---- edge (fused): TE=32, 128 threads, 8 CTAs/SM ----
__global__ __launch_bounds__(128, 8) void edge_kernel(
    const void*  __restrict__ ei_raw,
    const float* __restrict__ last_update,
    const float* __restrict__ t,
    const float* __restrict__ msg,
    const float* __restrict__ time_w,
    const float* __restrict__ time_b)
{
    extern __shared__ __half sA[];      // [TE][SAH] fp16 attr tile (10.75KB)
    __half2* eS = (__half2*)sA;         // [TE][SEH] fp16 e-result, overlays sA
    __shared__ int s_src[TE], s_dst[TE];

    const int tid = threadIdx.x;
    const int e0  = blockIdx.x * TE;
    const int wid = tid >> 5, lane = tid & 31;   // 4 warps

    // phase 1+2a (warp-local): warp w owns edges wid*8 + j, j=0..7.
    // Lanes 0..7 load indices+rel; broadcast rel via shfl.
    {
        int src = 0, dst = 0; float rel = 0.f;
        if (lane < 8) {
            const int eg = e0 + wid * 8 + lane;
            if (eg < NE) {
                if (g_idx64) {
                    const long long* p = (const long long*)ei_raw;
                    src = (int)__ldg(p + eg); dst = (int)__ldg(p + NE + eg);
                } else {
                    const int* p = (const int*)ei_raw;
                    src = __ldg(p + eg); dst = __ldg(p + NE + eg);
                }
                rel = __ldg(last_update + src) - __ldg(t + eg);
            }
            s_src[wid * 8 + lane] = src;
            s_dst[wid * 8 + lane] = dst;
        }
        const float tw = __ldg(time_w + lane);
        const float tb = __ldg(time_b + lane);
        #pragma unroll
        for (int j = 0; j < 8; j++) {
            const int e = wid * 8 + j;
            const float rj = __shfl_sync(0xffffffffu, rel, j);
            float v = 0.f;
            if (e0 + e < NE) v = __cosf(fmaf(rj, tw, tb));
            sA[e * SAH + lane] = __float2half(v);
        }
    }
    // phase 2b: msg cols [32,160)
    for (int i = tid; i < TE * 32; i += 128) {
        const int e = i >> 5, q = i & 31;
        float4 m = make_float4(0, 0, 0, 0);
        if (e0 + e < NE) m = __ldg((const float4*)(msg + (size_t)(e0 + e) * D) + q);
        __half2* p = (__half2*)(sA + e * SAH + TDIM + 4 * q);
        p[0] = __floats2half2_rn(m.x, m.y);
        p[1] = __floats2half2_rn(m.z, m.w);
    }
    __syncthreads();

    // phase 3: GEMM. 4 warps = 2(M) x 2(N); warp tile 16x64.
    const int g = lane >> 2, tg = lane & 3;
    const int wm = wid & 1, wn = wid >> 1;

    float acc[8][4];
    #pragma unroll
    for (int ni = 0; ni < 8; ni++)
        #pragma unroll
        for (int r = 0; r < 4; r++) acc[ni][r] = 0.f;

    const __half*  Abase = sA + (wm * 16 + g) * SAH + 2 * tg;
    const __half2* Bb    = g_we_h2 + wn * 64 + g * 8;

    #pragma unroll
    for (int ks = 0; ks < 10; ks++) {             // 10 k16-steps, K=160
        const int k0 = ks * 16;
        unsigned a[4];
        a[0] = *(const unsigned*)(Abase + k0);
        a[1] = *(const unsigned*)(Abase + 8 * SAH + k0);
        a[2] = *(const unsigned*)(Abase + k0 + 8);
        a[3] = *(const unsigned*)(Abase + 8 * SAH + k0 + 8);
        const uint4* bp0 = (const uint4*)(Bb + (size_t)(ks * 8 + tg) * D);
        const uint4* bp1 = (const uint4*)(Bb + (size_t)(ks * 8 + tg + 4) * D);
        const uint4 u0 = __ldg(bp0), u1 = __ldg(bp0 + 1);
        const uint4 v0 = __ldg(bp1), v1 = __ldg(bp1 + 1);
        const unsigned b0[8] = {u0.x, u0.y, u0.z, u0.w, u1.x, u1.y, u1.z, u1.w};
        const unsigned b1[8] = {v0.x, v0.y, v0.z, v0.w, v1.x, v1.y, v1.z, v1.w};
        #pragma unroll
        for (int ni = 0; ni < 8; ni++)
            mma_f16(acc[ni], a, b0[ni], b1[ni]);
    }
    __syncthreads();   // all warps done reading sA

    // phase 4: accumulators -> smem as fp16 (col map from proj: c = wn*64+ni*8+2tg)
    {
        const int r0 = wm * 16 + g;
        #pragma unroll
        for (int ni = 0; ni < 8; ni++) {
            const int h = wn * 32 + ni * 4 + tg;
            eS[r0 * SEH + h]       = __floats2half2_rn(acc[ni][0], acc[ni][1]);
            eS[(r0 + 8) * SEH + h] = __floats2half2_rn(acc[ni][2], acc[ni][3]);
        }
    }
    __syncthreads();

    // phase 5: attention epilogue, 2-deep gather pipelining. Warp = 8 edges.
    const int col = lane * 4;
    const int eB = e0 + wid * 8;
    int  src_n = s_src[wid * 8], dst_n = s_dst[wid * 8];
    uint2 q_n = make_uint2(0, 0), k_n = q_n, v_n = q_n;
    if (eB < NE) {
        q_n = __ldg((const uint2*)(g_qh + (size_t)dst_n * 64) + lane);
        k_n = __ldg((const uint2*)(g_kh + (size_t)src_n * 64) + lane);
        v_n = __ldg((const uint2*)(g_vh + (size_t)src_n * 64) + lane);
    }
    #pragma unroll
    for (int ii = 0; ii < 8; ii++) {
        const int eg = eB + ii;
        if (eg >= NE) break;
        const int dst = dst_n;
        const uint2 qraw = q_n, kraw = k_n, vraw = v_n;
        if (ii < 7 && eg + 1 < NE) {               // prefetch next edge
            src_n = s_src[wid * 8 + ii + 1];
            dst_n = s_dst[wid * 8 + ii + 1];
            q_n = __ldg((const uint2*)(g_qh + (size_t)dst_n * 64) + lane);
            k_n = __ldg((const uint2*)(g_kh + (size_t)src_n * 64) + lane);
            v_n = __ldg((const uint2*)(g_vh + (size_t)src_n * 64) + lane);
        }
        const uint2 eraw = *(const uint2*)(eS + (wid * 8 + ii) * SEH + 2 * lane);
        const float2 e01 = __half22float2(*(const __half2*)&eraw.x);
        const float2 e23 = __half22float2(*(const __half2*)&eraw.y);
        const float2 q01 = __half22float2(*(const __half2*)&qraw.x);
        const float2 q23 = __half22float2(*(const __half2*)&qraw.y);
        float2 k01 = __half22float2(*(const __half2*)&kraw.x);
        float2 k23 = __half22float2(*(const __half2*)&kraw.y);
        float2 v01 = __half22float2(*(const __half2*)&vraw.x);
        float2 v23 = __half22float2(*(const __half2*)&vraw.y);
        k01.x += e01.x; k01.y += e01.y; k23.x += e23.x; k23.y += e23.y;
        v01.x += e01.x; v01.y += e01.y; v23.x += e23.x; v23.y += e23.y;

        float p = q01.x * k01.x + q01.y * k01.y + q23.x * k23.x + q23.y * k23.y;
        p += __shfl_xor_sync(0xffffffffu, p, 1);
        p += __shfl_xor_sync(0xffffffffu, p, 2);
        p += __shfl_xor_sync(0xffffffffu, p, 4);
        p += __shfl_xor_sync(0xffffffffu, p, 8);
        const float ex = __expf(p * 0.125f);   // arg in [-3,3]; exact softmax w/o max-sub

        red_v4(g_agg + (size_t)dst * D + col,
               ex * v01.x, ex * v01.y, ex * v23.x, ex * v23.y);
        if ((lane & 15) == 0)
            red_1(&g_sum[dst * 2 + (lane >> 4)], ex);
    }
}

__global__ void finalize_kernel(float* __restrict__ out) {
    int idx = blockIdx.x * blockDim.x + threadIdx.x;
    if (idx >= NN * 32) return;
    const int n = idx >> 5;
    const int h = (idx & 31) >> 4;
    const float inv = 1.0f / (g_sum[n * 2 + h] + 1e-16f);
    float4 a = ((const float4*)g_agg)[idx];
    float4 o = ((float4*)out)[idx];
    o.x += a.x * inv; o.y += a.y * inv; o.z += a.z * inv; o.w += a.w * inv;
    ((float4*)out)[idx] = o;
}

extern "C" void kernel_launch(void* const* d_in, const int* in_sizes, int n_in,
                              void* d_out, int out_size) {
    const float* x           = (const float*)d_in[0];
    const float* last_update = (const float*)d_in[1];
    const void*  ei          = d_in[2];
    const float* t           = (const float*)d_in[3];
    const float* msg         = (const float*)d_in[4];
    const float* time_w      = (const float*)d_in[5];
    const float* time_b      = (const float*)d_in[6];
    const float* Wq          = (const float*)d_in[7];
    const float* bq          = (const float*)d_in[8];
    const float* Wk          = (const float*)d_in[9];
    const float* bk          = (const float*)d_in[10];
    const float* Wv          = (const float*)d_in[11];
    const float* bv          = (const float*)d_in[12];
    const float* We          = (const float*)d_in[13];
    const float* Ws          = (const float*)d_in[14];
    const float* bs          = (const float*)d_in[15];
    float* out = (float*)d_out;

    const int smem_e1 = TE * SAH * 2;     // 10,752 bytes
    const int smem_px = 128 * SXH * 2;    // 34,816 bytes
    static int configured = 0;
    if (!configured) {
        cudaFuncSetAttribute(edge_kernel,
                             cudaFuncAttributeMaxDynamicSharedMemorySize, smem_e1);
        cudaFuncSetAttribute(proj_kernel,
                             cudaFuncAttributeMaxDynamicSharedMemorySize, smem_px);
        configured = 1;
    }

    prep_kernel<<<592, 256>>>((const long long*)ei, We, Wq, Wk, Wv, Ws);
    proj_kernel<<<dim3((NN + 127) / 128, 4), 256, smem_px>>>(x, bq, bk, bv, bs, out);
    edge_kernel<<<(NE + TE - 1) / TE, 128, smem_e1>>>(ei, last_update, t, msg,
                                                      time_w, time_b);
    finalize_kernel<<<(NN * 32 + 255) / 256, 256>>>(out);
}

// round 16
// speedup vs baseline: 1.3520x; 1.3520x over previous
#include <cuda_runtime.h>
#include <cuda_fp16.h>

#define NN 50000
#define NE 500000
#define D 128
#define TDIM 32
#define EDIM 160
#define TE 64         // edges per block (edge kernel)
#define SAH 168       // attr tile smem stride (halves)
#define SEH 68        // e-result smem stride (half2)
#define SXH 136       // x tile smem stride (halves)

// ---- scratch (no cudaMalloc allowed) ----
__device__ __half2 g_qh[NN * 64];
__device__ __half2 g_kh[NN * 64];
__device__ __half2 g_vh[NN * 64];
__device__ float   g_agg[NN * D];
__device__ float   g_sum[NN * 2];
__device__ __half2 g_we_h2[80 * D];          // pre-swizzled fp16 We (k-pairs)
__device__ __half2 g_w_h2[4 * 64 * D];       // pre-swizzled fp16 Wq|Wk|Wv|Wskip
__device__ int     g_idx64;

// ---- helpers ----
__device__ __forceinline__ void red_v4(float* p, float a, float b, float c, float d) {
    asm volatile("red.global.add.v4.f32 [%0], {%1,%2,%3,%4};"
                 :: "l"(p), "f"(a), "f"(b), "f"(c), "f"(d) : "memory");
}
__device__ __forceinline__ void red_1(float* p, float a) {
    asm volatile("red.global.add.f32 [%0], %1;" :: "l"(p), "f"(a) : "memory");
}
__device__ __forceinline__ void mma_f16(float* c, const unsigned* a,
                                        unsigned b0, unsigned b1) {
    asm volatile(
        "mma.sync.aligned.m16n8k16.row.col.f32.f16.f16.f32 "
        "{%0,%1,%2,%3}, {%4,%5,%6,%7}, {%8,%9}, {%0,%1,%2,%3};"
        : "+f"(c[0]), "+f"(c[1]), "+f"(c[2]), "+f"(c[3])
        : "r"(a[0]), "r"(a[1]), "r"(a[2]), "r"(a[3]), "r"(b0), "r"(b1));
}

// ---- prep: detect idx width + pre-swizzle weights + zero agg/sum (one launch) ----
__global__ void prep_kernel(const long long* __restrict__ ei,
                            const float* __restrict__ We,
                            const float* __restrict__ Wq,
                            const float* __restrict__ Wk,
                            const float* __restrict__ Wv,
                            const float* __restrict__ Ws) {
    const int i = blockIdx.x * blockDim.x + threadIdx.x;
    const int stride = gridDim.x * blockDim.x;
    if (i == 0) {
        bool ok = true;
        #pragma unroll
        for (int j = 0; j < 16; j++) {
            long long v = ei[j];
            if (v < 0 || v >= NN) ok = false;
        }
        g_idx64 = ok ? 1 : 0;
    }
    if (i < 80 * D) {                     // We: 80 k-pairs x 128 cols
        const int p = i >> 7, c = i & 127;
        const int s = (c >> 6) * 64 + (c & 7) * 8 + ((c >> 3) & 7);
        g_we_h2[p * D + s] = __floats2half2_rn(__ldg(We + (2 * p) * D + c),
                                               __ldg(We + (2 * p + 1) * D + c));
    }
    if (i < 4 * 64 * D) {                 // Wq|Wk|Wv|Ws: 64 k-pairs each
        const int mat = i >> 13, rem = i & 8191;
        const int p = rem >> 7, c = rem & 127;
        const int s = (c >> 6) * 64 + (c & 7) * 8 + ((c >> 3) & 7);
        const float* W = (mat == 0) ? Wq : (mat == 1) ? Wk : (mat == 2) ? Wv : Ws;
        g_w_h2[mat * 64 * D + p * D + s] =
            __floats2half2_rn(__ldg(W + (2 * p) * D + c), __ldg(W + (2 * p + 1) * D + c));
    }
    const float4 z = make_float4(0, 0, 0, 0);
    for (int j = i; j < NN * 32; j += stride) ((float4*)g_agg)[j] = z;
    for (int j = i; j < NN / 2;  j += stride) ((float4*)g_sum)[j] = z;
}

// ---- proj (fp16 mma): q,k,v,skip = x @ W + b. One block does all 4 matrices. ----
__global__ __launch_bounds__(256, 2) void proj_kernel(
    const float* __restrict__ x,
    const float* __restrict__ bq, const float* __restrict__ bk,
    const float* __restrict__ bv, const float* __restrict__ bs,
    float* __restrict__ out)
{
    extern __shared__ __half sX[];   // [128][SXH] fp16 x tile (34.8KB)
    const int tid = threadIdx.x;
    const int n0  = blockIdx.x * 128;

    for (int i = tid; i < 128 * 32; i += 256) {
        const int n = i >> 5, q = i & 31;
        float4 m = make_float4(0, 0, 0, 0);
        if (n0 + n < NN) m = __ldg((const float4*)(x + (size_t)(n0 + n) * D) + q);
        __half2* p = (__half2*)(sX + n * SXH + 4 * q);
        p[0] = __floats2half2_rn(m.x, m.y);
        p[1] = __floats2half2_rn(m.z, m.w);
    }
    __syncthreads();

    const int wid = tid >> 5, lane = tid & 31;
    const int g = lane >> 2, tg = lane & 3;
    const int wm = wid & 3, wn = wid >> 2;

    const __half* Abase = sX + (wm * 32 + g) * SXH + 2 * tg;

    #pragma unroll
    for (int mat = 0; mat < 4; mat++) {
        float acc[2][8][4];
        #pragma unroll
        for (int mi = 0; mi < 2; mi++)
            #pragma unroll
            for (int ni = 0; ni < 8; ni++)
                #pragma unroll
                for (int r = 0; r < 4; r++) acc[mi][ni][r] = 0.f;

        const __half2* Bb = g_w_h2 + mat * 64 * D + wn * 64 + g * 8;

        #pragma unroll
        for (int ks = 0; ks < 8; ks++) {             // 8 k16-steps, K=128
            const int k0 = ks * 16;
            unsigned a[2][4];
            #pragma unroll
            for (int mi = 0; mi < 2; mi++) {
                const __half* ap = Abase + mi * 16 * SXH + k0;
                a[mi][0] = *(const unsigned*)(ap);
                a[mi][1] = *(const unsigned*)(ap + 8 * SXH);
                a[mi][2] = *(const unsigned*)(ap + 8);
                a[mi][3] = *(const unsigned*)(ap + 8 * SXH + 8);
            }
            const uint4* bp0 = (const uint4*)(Bb + (size_t)(ks * 8 + tg) * D);
            const uint4* bp1 = (const uint4*)(Bb + (size_t)(ks * 8 + tg + 4) * D);
            const uint4 u0 = __ldg(bp0), u1 = __ldg(bp0 + 1);
            const uint4 v0 = __ldg(bp1), v1 = __ldg(bp1 + 1);
            const unsigned b0[8] = {u0.x, u0.y, u0.z, u0.w, u1.x, u1.y, u1.z, u1.w};
            const unsigned b1[8] = {v0.x, v0.y, v0.z, v0.w, v1.x, v1.y, v1.z, v1.w};
            #pragma unroll
            for (int ni = 0; ni < 8; ni++) {
                mma_f16(acc[0][ni], a[0], b0[ni], b1[ni]);
                mma_f16(acc[1][ni], a[1], b0[ni], b1[ni]);
            }
        }

        const float* bias = (mat == 0) ? bq : (mat == 1) ? bk : (mat == 2) ? bv : bs;

        #pragma unroll
        for (int mi = 0; mi < 2; mi++) {
            const int r0 = n0 + wm * 32 + mi * 16 + g;
            #pragma unroll
            for (int ni = 0; ni < 8; ni++) {
                const int c = wn * 64 + ni * 8 + 2 * tg;
                const float2 bb = __ldg((const float2*)(bias + c));
                if (mat == 3) {
                    if (r0 < NN)
                        *(float2*)(out + (size_t)r0 * D + c) =
                            make_float2(acc[mi][ni][0] + bb.x, acc[mi][ni][1] + bb.y);
                    if (r0 + 8 < NN)
                        *(float2*)(out + (size_t)(r0 + 8) * D + c) =
                            make_float2(acc[mi][ni][2] + bb.x, acc[mi][ni][3] + bb.y);
                } else {
                    __half2* dst = (mat == 0) ? g_qh : (mat == 1) ? g_kh : g_vh;
                    const int hc = c >> 1;
                    if (r0 < NN)
                        dst[(size_t)r0 * 64 + hc] =
                            __floats2half2_rn(acc[mi][ni][0] + bb.x, acc[mi][ni][1] + bb.y);
                    if (r0 + 8 < NN)
                        dst[(size_t)(r0 + 8) * 64 + hc] =
                            __floats2half2_rn(acc[mi][ni][2] + bb.x, acc[mi][ni][3] + bb.y);
                }
            }
        }
    }
}

// ---- edge (fused): attr build + fp16 GEMM + attention epilogue. 4 CTAs/SM ----
__global__ __launch_bounds__(256, 4) void edge_kernel(
    const void*  __restrict__ ei_raw,
    const float* __restrict__ last_update,
    const float* __restrict__ t,
    const float* __restrict__ msg,
    const float* __restrict__ time_w,
    const float* __restrict__ time_b)
{
    extern __shared__ __half sA[];      // [TE][SAH] fp16 attr tile (21.5KB)
    __half2* eS = (__half2*)sA;         // [TE][SEH] fp16 e-result, overlays sA
    __shared__ int s_src[TE], s_dst[TE];

    const int tid = threadIdx.x;
    const int e0  = blockIdx.x * TE;
    const int wid = tid >> 5, lane = tid & 31;

    // phase 1+2a (warp-local, no block sync): warp w owns edges e = w + 8j.
    {
        int src = 0, dst = 0; float rel = 0.f;
        if (lane < 8) {
            const int eg = e0 + wid + 8 * lane;
            if (eg < NE) {
                if (g_idx64) {
                    const long long* p = (const long long*)ei_raw;
                    src = (int)__ldg(p + eg); dst = (int)__ldg(p + NE + eg);
                } else {
                    const int* p = (const int*)ei_raw;
                    src = __ldg(p + eg); dst = __ldg(p + NE + eg);
                }
                rel = __ldg(last_update + src) - __ldg(t + eg);
            }
            s_src[wid + 8 * lane] = src;
            s_dst[wid + 8 * lane] = dst;
        }
        const float tw = __ldg(time_w + lane);
        const float tb = __ldg(time_b + lane);
        #pragma unroll
        for (int j = 0; j < 8; j++) {
            const int e = wid + 8 * j;
            const float rj = __shfl_sync(0xffffffffu, rel, j);
            float v = 0.f;
            if (e0 + e < NE) v = __cosf(fmaf(rj, tw, tb));
            sA[e * SAH + lane] = __float2half(v);
        }
    }
    // phase 2b: msg cols [32,160)
    for (int i = tid; i < TE * 32; i += 256) {
        const int e = i >> 5, q = i & 31;
        float4 m = make_float4(0, 0, 0, 0);
        if (e0 + e < NE) m = __ldg((const float4*)(msg + (size_t)(e0 + e) * D) + q);
        __half2* p = (__half2*)(sA + e * SAH + TDIM + 4 * q);
        p[0] = __floats2half2_rn(m.x, m.y);
        p[1] = __floats2half2_rn(m.z, m.w);
    }
    __syncthreads();

    // phase 3: GEMM. 8 warps = 2(M) x 4(N); warp tile 32x32.
    const int g = lane >> 2, tg = lane & 3;
    const int wm = wid & 1, wn = wid >> 1;
    const int half = wn >> 1, w1 = wn & 1;

    float acc[2][4][4];
    #pragma unroll
    for (int mi = 0; mi < 2; mi++)
        #pragma unroll
        for (int ni = 0; ni < 4; ni++)
            #pragma unroll
            for (int r = 0; r < 4; r++) acc[mi][ni][r] = 0.f;

    const __half*  Abase = sA + (wm * 32 + g) * SAH + 2 * tg;
    const __half2* Bb    = g_we_h2 + half * 64 + g * 8 + w1 * 4;

    #pragma unroll
    for (int ks = 0; ks < 10; ks++) {             // 10 k16-steps, K=160
        const int k0 = ks * 16;
        unsigned a[2][4];
        #pragma unroll
        for (int mi = 0; mi < 2; mi++) {
            const __half* ap = Abase + mi * 16 * SAH + k0;
            a[mi][0] = *(const unsigned*)(ap);
            a[mi][1] = *(const unsigned*)(ap + 8 * SAH);
            a[mi][2] = *(const unsigned*)(ap + 8);
            a[mi][3] = *(const unsigned*)(ap + 8 * SAH + 8);
        }
        const uint4 u = __ldg((const uint4*)(Bb + (size_t)(ks * 8 + tg) * D));
        const uint4 v = __ldg((const uint4*)(Bb + (size_t)(ks * 8 + tg + 4) * D));
        const unsigned b0[4] = {u.x, u.y, u.z, u.w};
        const unsigned b1[4] = {v.x, v.y, v.z, v.w};
        #pragma unroll
        for (int ni = 0; ni < 4; ni++) {
            mma_f16(acc[0][ni], a[0], b0[ni], b1[ni]);
            mma_f16(acc[1][ni], a[1], b0[ni], b1[ni]);
        }
    }
    __syncthreads();   // all warps done reading sA

    // phase 4: accumulators -> smem as fp16
    #pragma unroll
    for (int mi = 0; mi < 2; mi++) {
        const int r0 = wm * 32 + mi * 16 + g;
        #pragma unroll
        for (int ni = 0; ni < 4; ni++) {
            const int h = half * 32 + (w1 * 4 + ni) * 4 + tg;
            eS[r0 * SEH + h]       = __floats2half2_rn(acc[mi][ni][0], acc[mi][ni][1]);
            eS[(r0 + 8) * SEH + h] = __floats2half2_rn(acc[mi][ni][2], acc[mi][ni][3]);
        }
    }
    __syncthreads();

    // phase 5: attention epilogue, 2-deep gather pipelining. Warp = 8 edges.
    const int col = lane * 4;
    const int eB = e0 + wid * 8;
    int  src_n = s_src[wid * 8], dst_n = s_dst[wid * 8];
    uint2 q_n = make_uint2(0, 0), k_n = q_n, v_n = q_n;
    if (eB < NE) {
        q_n = __ldg((const uint2*)(g_qh + (size_t)dst_n * 64) + lane);
        k_n = __ldg((const uint2*)(g_kh + (size_t)src_n * 64) + lane);
        v_n = __ldg((const uint2*)(g_vh + (size_t)src_n * 64) + lane);
    }
    #pragma unroll
    for (int ii = 0; ii < 8; ii++) {
        const int eg = eB + ii;
        if (eg >= NE) break;
        const int dst = dst_n;
        const uint2 qraw = q_n, kraw = k_n, vraw = v_n;
        if (ii < 7 && eg + 1 < NE) {               // prefetch next edge
            src_n = s_src[wid * 8 + ii + 1];
            dst_n = s_dst[wid * 8 + ii + 1];
            q_n = __ldg((const uint2*)(g_qh + (size_t)dst_n * 64) + lane);
            k_n = __ldg((const uint2*)(g_kh + (size_t)src_n * 64) + lane);
            v_n = __ldg((const uint2*)(g_vh + (size_t)src_n * 64) + lane);
        }
        const uint2 eraw = *(const uint2*)(eS + (wid * 8 + ii) * SEH + 2 * lane);
        const float2 e01 = __half22float2(*(const __half2*)&eraw.x);
        const float2 e23 = __half22float2(*(const __half2*)&eraw.y);
        const float2 q01 = __half22float2(*(const __half2*)&qraw.x);
        const float2 q23 = __half22float2(*(const __half2*)&qraw.y);
        float2 k01 = __half22float2(*(const __half2*)&kraw.x);
        float2 k23 = __half22float2(*(const __half2*)&kraw.y);
        float2 v01 = __half22float2(*(const __half2*)&vraw.x);
        float2 v23 = __half22float2(*(const __half2*)&vraw.y);
        k01.x += e01.x; k01.y += e01.y; k23.x += e23.x; k23.y += e23.y;
        v01.x += e01.x; v01.y += e01.y; v23.x += e23.x; v23.y += e23.y;

        float p = q01.x * k01.x + q01.y * k01.y + q23.x * k23.x + q23.y * k23.y;
        p += __shfl_xor_sync(0xffffffffu, p, 1);
        p += __shfl_xor_sync(0xffffffffu, p, 2);
        p += __shfl_xor_sync(0xffffffffu, p, 4);
        p += __shfl_xor_sync(0xffffffffu, p, 8);
        const float ex = __expf(p * 0.125f);   // arg in [-3,3]; exact softmax w/o max-sub

        red_v4(g_agg + (size_t)dst * D + col,
               ex * v01.x, ex * v01.y, ex * v23.x, ex * v23.y);
        if ((lane & 15) == 0)
            red_1(&g_sum[dst * 2 + (lane >> 4)], ex);
    }
}

__global__ void finalize_kernel(float* __restrict__ out) {
    int idx = blockIdx.x * blockDim.x + threadIdx.x;
    if (idx >= NN * 32) return;
    const int n = idx >> 5;
    const int h = (idx & 31) >> 4;
    const float inv = 1.0f / (g_sum[n * 2 + h] + 1e-16f);
    float4 a = ((const float4*)g_agg)[idx];
    float4 o = ((float4*)out)[idx];
    o.x += a.x * inv; o.y += a.y * inv; o.z += a.z * inv; o.w += a.w * inv;
    ((float4*)out)[idx] = o;
}

extern "C" void kernel_launch(void* const* d_in, const int* in_sizes, int n_in,
                              void* d_out, int out_size) {
    const float* x           = (const float*)d_in[0];
    const float* last_update = (const float*)d_in[1];
    const void*  ei          = d_in[2];
    const float* t           = (const float*)d_in[3];
    const float* msg         = (const float*)d_in[4];
    const float* time_w      = (const float*)d_in[5];
    const float* time_b      = (const float*)d_in[6];
    const float* Wq          = (const float*)d_in[7];
    const float* bq          = (const float*)d_in[8];
    const float* Wk          = (const float*)d_in[9];
    const float* bk          = (const float*)d_in[10];
    const float* Wv          = (const float*)d_in[11];
    const float* bv          = (const float*)d_in[12];
    const float* We          = (const float*)d_in[13];
    const float* Ws          = (const float*)d_in[14];
    const float* bs          = (const float*)d_in[15];
    float* out = (float*)d_out;

    const int smem_e1 = TE * SAH * 2;     // 21,504 bytes
    const int smem_px = 128 * SXH * 2;    // 34,816 bytes
    static int configured = 0;
    if (!configured) {
        cudaFuncSetAttribute(edge_kernel,
                             cudaFuncAttributeMaxDynamicSharedMemorySize, smem_e1);
        cudaFuncSetAttribute(proj_kernel,
                             cudaFuncAttributeMaxDynamicSharedMemorySize, smem_px);
        configured = 1;
    }

    prep_kernel<<<592, 256>>>((const long long*)ei, We, Wq, Wk, Wv, Ws);
    proj_kernel<<<(NN + 127) / 128, 256, smem_px>>>(x, bq, bk, bv, bs, out);
    edge_kernel<<<(NE + TE - 1) / TE, 256, smem_e1>>>(ei, last_update, t, msg,
                                                      time_w, time_b);
    finalize_kernel<<<(NN * 32 + 255) / 256, 256>>>(out);
}